// round 1
// baseline (speedup 1.0000x reference)
#include <cuda_runtime.h>
#include <cuda_bf16.h>
#include <math.h>

// Problem constants
#define BATCH 4
#define SEQ   2048
#define CH    1024
#define NH    16
#define HD    64        // head dim
#define M_ROWS (BATCH*SEQ)          // 8192
#define QKV_N  (3*CH)               // 3072

// ---------------- scratch (device globals: allocation-guard safe) ----------
__device__ float g_qkv[(size_t)M_ROWS * QKV_N];   // [B*T, 3C]  (96 MB)
__device__ float g_y  [(size_t)M_ROWS * CH];      // [B*T, C]   (32 MB)

// ---------------- SGEMM: C = A @ B + bias, 128x128x8, 8x8 microtile --------
#define BM 128
#define BN 128
#define BK 8
#define TM 8
#define TN 8

__global__ __launch_bounds__(256, 2)
void sgemm_bias_kernel(const float* __restrict__ A,
                       const float* __restrict__ B,
                       const float* __restrict__ bias,
                       float* __restrict__ C,
                       int M, int N, int K)
{
    __shared__ float As[BK][BM];
    __shared__ float Bs[BK][BN];

    const int tid = threadIdx.x;
    const int bx = blockIdx.x;   // N tile
    const int by = blockIdx.y;   // M tile

    const float* Ab = A + (size_t)by * BM * K;
    const float* Bb = B + (size_t)bx * BN;

    const int tx = tid % 16;     // 16 threads along N
    const int ty = tid / 16;     // 16 threads along M

    const int arow = tid >> 1;          // 0..127
    const int acol = (tid & 1) * 4;     // 0 or 4
    const int brow = tid >> 5;          // 0..7
    const int bcol = (tid & 31) * 4;    // 0..124

    float acc[TM][TN];
    #pragma unroll
    for (int i = 0; i < TM; i++)
        #pragma unroll
        for (int j = 0; j < TN; j++) acc[i][j] = 0.f;

    for (int k0 = 0; k0 < K; k0 += BK) {
        float4 a4 = *(const float4*)(Ab + (size_t)arow * K + k0 + acol);
        As[acol + 0][arow] = a4.x;
        As[acol + 1][arow] = a4.y;
        As[acol + 2][arow] = a4.z;
        As[acol + 3][arow] = a4.w;
        *(float4*)&Bs[brow][bcol] =
            *(const float4*)(Bb + (size_t)(k0 + brow) * N + bcol);
        __syncthreads();

        #pragma unroll
        for (int k = 0; k < BK; k++) {
            float ra[TM], rb[TN];
            float4 ra0 = *(const float4*)&As[k][ty * TM];
            float4 ra1 = *(const float4*)&As[k][ty * TM + 4];
            ra[0]=ra0.x; ra[1]=ra0.y; ra[2]=ra0.z; ra[3]=ra0.w;
            ra[4]=ra1.x; ra[5]=ra1.y; ra[6]=ra1.z; ra[7]=ra1.w;
            float4 rb0 = *(const float4*)&Bs[k][tx * TN];
            float4 rb1 = *(const float4*)&Bs[k][tx * TN + 4];
            rb[0]=rb0.x; rb[1]=rb0.y; rb[2]=rb0.z; rb[3]=rb0.w;
            rb[4]=rb1.x; rb[5]=rb1.y; rb[6]=rb1.z; rb[7]=rb1.w;
            #pragma unroll
            for (int i = 0; i < TM; i++)
                #pragma unroll
                for (int j = 0; j < TN; j++)
                    acc[i][j] += ra[i] * rb[j];
        }
        __syncthreads();
    }

    #pragma unroll
    for (int i = 0; i < TM; i++) {
        const int row = by * BM + ty * TM + i;
        #pragma unroll
        for (int j = 0; j < TN; j += 4) {
            const int col = bx * BN + tx * TN + j;
            float4 o;
            o.x = acc[i][j + 0] + bias[col + 0];
            o.y = acc[i][j + 1] + bias[col + 1];
            o.z = acc[i][j + 2] + bias[col + 2];
            o.w = acc[i][j + 3] + bias[col + 3];
            *(float4*)(C + (size_t)row * N + col) = o;
        }
    }
}

// ---------------- Flash attention (fp32, per-thread query row) -------------
// Block: 128 threads = 128 query rows for one (b, h).
// qkv layout: [B*T, 3C]; q at +h*HD, k at +C+h*HD, v at +2C+h*HD.
#define AT_ROWS 128
#define AT_TK   64

__global__ __launch_bounds__(AT_ROWS)
void attn_kernel(const float* __restrict__ qkv, float* __restrict__ y)
{
    __shared__ float Ks[AT_TK][HD];
    __shared__ float Vs[AT_TK][HD];

    const int b  = blockIdx.z;
    const int h  = blockIdx.y;
    const int qi = blockIdx.x * AT_ROWS + threadIdx.x;

    const float scale = 0.125f;  // 1/sqrt(64)

    float q[HD];
    {
        const float* qp = qkv + ((size_t)(b * SEQ + qi) * QKV_N) + h * HD;
        #pragma unroll
        for (int d = 0; d < HD; d += 4) {
            float4 t = *(const float4*)(qp + d);
            q[d] = t.x * scale; q[d+1] = t.y * scale;
            q[d+2] = t.z * scale; q[d+3] = t.w * scale;
        }
    }

    float O[HD];
    #pragma unroll
    for (int d = 0; d < HD; d++) O[d] = 0.f;
    float m = -1e30f, l = 0.f;

    const int nkt = (blockIdx.x * AT_ROWS + AT_ROWS) / AT_TK;  // causal tile count

    for (int kt = 0; kt < nkt; kt++) {
        // cooperative K/V tile load (float4, coalesced)
        const float* kbase = qkv + ((size_t)(b * SEQ + kt * AT_TK) * QKV_N) + CH + h * HD;
        #pragma unroll
        for (int it = 0; it < (AT_TK * HD / 4) / AT_ROWS; it++) {
            int idx = it * AT_ROWS + threadIdx.x;
            int j = idx / (HD / 4);
            int c = (idx % (HD / 4)) * 4;
            const float* src = kbase + (size_t)j * QKV_N + c;
            *(float4*)&Ks[j][c] = *(const float4*)(src);
            *(float4*)&Vs[j][c] = *(const float4*)(src + CH);
        }
        __syncthreads();

        const int jmax = min(AT_TK, qi - kt * AT_TK + 1);
        for (int j = 0; j < jmax; j++) {
            float s = 0.f;
            #pragma unroll
            for (int d = 0; d < HD; d += 4) {
                float4 kk = *(const float4*)&Ks[j][d];
                s += q[d] * kk.x + q[d+1] * kk.y + q[d+2] * kk.z + q[d+3] * kk.w;
            }
            if (s > m) {
                float coef = __expf(m - s);
                l *= coef;
                #pragma unroll
                for (int d = 0; d < HD; d++) O[d] *= coef;
                m = s;
            }
            float p = __expf(s - m);
            l += p;
            #pragma unroll
            for (int d = 0; d < HD; d += 4) {
                float4 vv = *(const float4*)&Vs[j][d];
                O[d]   += p * vv.x; O[d+1] += p * vv.y;
                O[d+2] += p * vv.z; O[d+3] += p * vv.w;
            }
        }
        __syncthreads();
    }

    const float inv = 1.f / l;
    float* yp = y + ((size_t)(b * SEQ + qi) * CH) + h * HD;
    #pragma unroll
    for (int d = 0; d < HD; d += 4) {
        float4 o;
        o.x = O[d] * inv; o.y = O[d+1] * inv;
        o.z = O[d+2] * inv; o.w = O[d+3] * inv;
        *(float4*)(yp + d) = o;
    }
}

// ---------------- launch --------------------------------------------------
extern "C" void kernel_launch(void* const* d_in, const int* in_sizes, int n_in,
                              void* d_out, int out_size)
{
    const float* x      = (const float*)d_in[0];   // [B,T,C]
    const float* w_qkv  = (const float*)d_in[1];   // [C,3C]
    const float* b_qkv  = (const float*)d_in[2];   // [3C]
    const float* w_proj = (const float*)d_in[3];   // [C,C]
    const float* b_proj = (const float*)d_in[4];   // [C]
    float* out = (float*)d_out;

    float* qkv = nullptr;
    float* y   = nullptr;
    cudaGetSymbolAddress((void**)&qkv, g_qkv);
    cudaGetSymbolAddress((void**)&y,   g_y);

    // 1) QKV GEMM: [8192,1024] @ [1024,3072] + bias -> g_qkv
    {
        dim3 grid(QKV_N / BN, M_ROWS / BM);
        sgemm_bias_kernel<<<grid, 256>>>(x, w_qkv, b_qkv, qkv,
                                         M_ROWS, QKV_N, CH);
    }

    // 2) causal flash attention -> g_y
    {
        dim3 grid(SEQ / AT_ROWS, NH, BATCH);
        attn_kernel<<<grid, AT_ROWS>>>(qkv, y);
    }

    // 3) proj GEMM: [8192,1024] @ [1024,1024] + bias -> out
    {
        dim3 grid(CH / BN, M_ROWS / BM);
        sgemm_bias_kernel<<<grid, 256>>>(y, w_proj, b_proj, out,
                                         M_ROWS, CH, CH);
    }
}

// round 3
// speedup vs baseline: 1.3897x; 1.3897x over previous
#include <cuda_runtime.h>
#include <cuda_bf16.h>
#include <cstdint>
#include <math.h>

// Problem constants
#define BATCH 4
#define SEQ   2048
#define CH    1024
#define NH    16
#define HD    64
#define M_ROWS (BATCH*SEQ)          // 8192
#define QKV_N  (3*CH)               // 3072

// ---------------- scratch (device globals: allocation-guard safe) ----------
__device__ float g_qkv[(size_t)M_ROWS * QKV_N];   // [B*T, 3C]
__device__ float g_y  [(size_t)M_ROWS * CH];      // [B*T, C]

// ======================= tf32 tensor-core GEMM ============================
// C[M,N] = A[M,K] @ B[K,N] + bias, tiles 128x128x16, 4 warps, warp tile 64x64,
// mma.sync.m16n8k8.tf32, cp.async double-buffered.
#define GBM 128
#define GBN 128
#define GBK 16
#define AS_STRIDE 20    // BK + 4 pad  (conflict-free A-frag LDS)
#define BS_STRIDE 136   // BN + 8 pad  (conflict-free B-frag LDS)

__device__ __forceinline__ unsigned f2tf32(float f) {
    unsigned u; asm("cvt.rna.tf32.f32 %0, %1;" : "=r"(u) : "f"(f)); return u;
}
__device__ __forceinline__ void mma_tf32(float c[4], const unsigned a[4], const unsigned b[2]) {
    asm volatile("mma.sync.aligned.m16n8k8.row.col.f32.tf32.tf32.f32 "
        "{%0,%1,%2,%3}, {%4,%5,%6,%7}, {%8,%9}, {%0,%1,%2,%3};"
        : "+f"(c[0]), "+f"(c[1]), "+f"(c[2]), "+f"(c[3])
        : "r"(a[0]), "r"(a[1]), "r"(a[2]), "r"(a[3]), "r"(b[0]), "r"(b[1]));
}
__device__ __forceinline__ void cp_async16(unsigned s, const void* g) {
    asm volatile("cp.async.ca.shared.global [%0], [%1], 16;" :: "r"(s), "l"(g));
}
__device__ __forceinline__ unsigned smem_u32(const void* p) {
    return (unsigned)__cvta_generic_to_shared(p);
}

__global__ __launch_bounds__(128, 2)
void gemm_tf32(const float* __restrict__ A, const float* __restrict__ B,
               const float* __restrict__ bias, float* __restrict__ C,
               int M, int N, int K)
{
    __shared__ __align__(16) float As[2][GBM][AS_STRIDE];   // [m][k]
    __shared__ __align__(16) float Bs[2][GBK][BS_STRIDE];   // [k][n]

    const int tid  = threadIdx.x;
    const int lane = tid & 31;
    const int warp = tid >> 5;
    const int wm = warp >> 1;           // 0..1
    const int wn = warp & 1;            // 0..1
    const int bx = blockIdx.x, by = blockIdx.y;

    float c[4][8][4];
    #pragma unroll
    for (int i = 0; i < 4; i++)
        #pragma unroll
        for (int j = 0; j < 8; j++)
            #pragma unroll
            for (int t = 0; t < 4; t++) c[i][j][t] = 0.f;

    // gmem->smem assignment
    const float* Arow  = A + (size_t)(by * GBM + tid) * K;          // thread's A row
    const int    bk    = tid >> 3;                                   // 0..15
    const int    bn4   = (tid & 7) * 4;                              // float col base
    const float* Bbase = B + (size_t)bk * N + (size_t)bx * GBN + bn4;

    const int NKT = K / GBK;

    // ---- prologue: stage 0 ----
    {
        #pragma unroll
        for (int k4 = 0; k4 < 4; k4++)
            cp_async16(smem_u32(&As[0][tid][k4 * 4]), Arow + k4 * 4);
        #pragma unroll
        for (int j = 0; j < 4; j++)
            cp_async16(smem_u32(&Bs[0][bk][bn4 + j * 32]), Bbase + j * 32);
        asm volatile("cp.async.commit_group;");
    }

    for (int kt = 0; kt < NKT; kt++) {
        const int buf = kt & 1;
        if (kt + 1 < NKT) {
            const int k0 = (kt + 1) * GBK;
            #pragma unroll
            for (int k4 = 0; k4 < 4; k4++)
                cp_async16(smem_u32(&As[buf ^ 1][tid][k4 * 4]), Arow + k0 + k4 * 4);
            #pragma unroll
            for (int j = 0; j < 4; j++)
                cp_async16(smem_u32(&Bs[buf ^ 1][bk][bn4 + j * 32]),
                           Bbase + (size_t)k0 * N + j * 32);
            asm volatile("cp.async.commit_group;");
            asm volatile("cp.async.wait_group 1;");
        } else {
            asm volatile("cp.async.wait_group 0;");
        }
        __syncthreads();

        #pragma unroll
        for (int ks = 0; ks < 2; ks++) {
            unsigned a[4][4], b[8][2];
            const int kk = ks * 8 + (lane & 3);
            const int r4 = lane >> 2;
            #pragma unroll
            for (int mf = 0; mf < 4; mf++) {
                const int m = wm * 64 + mf * 16 + r4;
                a[mf][0] = f2tf32(As[buf][m][kk]);
                a[mf][1] = f2tf32(As[buf][m + 8][kk]);
                a[mf][2] = f2tf32(As[buf][m][kk + 4]);
                a[mf][3] = f2tf32(As[buf][m + 8][kk + 4]);
            }
            #pragma unroll
            for (int nf = 0; nf < 8; nf++) {
                const int n = wn * 64 + nf * 8 + r4;
                b[nf][0] = f2tf32(Bs[buf][kk][n]);
                b[nf][1] = f2tf32(Bs[buf][kk + 4][n]);
            }
            #pragma unroll
            for (int mf = 0; mf < 4; mf++)
                #pragma unroll
                for (int nf = 0; nf < 8; nf++)
                    mma_tf32(c[mf][nf], a[mf], b[nf]);
        }
        __syncthreads();
    }

    // ---- epilogue: bias + store ----
    const int r0  = lane >> 2;
    const int c0l = (lane & 3) * 2;
    #pragma unroll
    for (int mf = 0; mf < 4; mf++) {
        const int row = by * GBM + wm * 64 + mf * 16 + r0;
        #pragma unroll
        for (int nf = 0; nf < 8; nf++) {
            const int col = bx * GBN + wn * 64 + nf * 8 + c0l;
            const float2 bb = *(const float2*)&bias[col];
            float2 o0, o1;
            o0.x = c[mf][nf][0] + bb.x; o0.y = c[mf][nf][1] + bb.y;
            o1.x = c[mf][nf][2] + bb.x; o1.y = c[mf][nf][3] + bb.y;
            *(float2*)(C + (size_t)row * N + col)       = o0;
            *(float2*)(C + (size_t)(row + 8) * N + col) = o1;
        }
    }
}

// ================= Flash attention (fp32, f32x2 packed FMA) ================
typedef unsigned long long u64;
__device__ __forceinline__ u64 pack2(float lo, float hi) {
    u64 r; asm("mov.b64 %0, {%1, %2};" : "=l"(r) : "f"(lo), "f"(hi)); return r;
}
__device__ __forceinline__ void unpack2(u64 v, float& lo, float& hi) {
    asm("mov.b64 {%0, %1}, %2;" : "=f"(lo), "=f"(hi) : "l"(v));
}
__device__ __forceinline__ u64 fma2(u64 a, u64 b, u64 c) {
    u64 d; asm("fma.rn.f32x2 %0, %1, %2, %3;" : "=l"(d) : "l"(a), "l"(b), "l"(c)); return d;
}
__device__ __forceinline__ u64 mul2(u64 a, u64 b) {
    u64 d; asm("mul.rn.f32x2 %0, %1, %2;" : "=l"(d) : "l"(a), "l"(b)); return d;
}

#define AT_ROWS 128
#define AT_TK   64
#define HD2     (HD/2)   // 32 packed lanes

__global__ __launch_bounds__(AT_ROWS)
void attn_kernel(const float* __restrict__ qkv, float* __restrict__ y)
{
    __shared__ __align__(16) float Ks[AT_TK][HD];
    __shared__ __align__(16) float Vs[AT_TK][HD];

    const int b  = blockIdx.z;
    const int h  = blockIdx.y;
    const int qi = blockIdx.x * AT_ROWS + threadIdx.x;

    const float scale = 0.125f;  // 1/sqrt(64)
    const u64 scale2 = pack2(scale, scale);

    u64 q2[HD2];
    {
        const float* qp = qkv + ((size_t)(b * SEQ + qi) * QKV_N) + h * HD;
        #pragma unroll
        for (int d = 0; d < HD2; d += 2) {
            float4 t = *(const float4*)(qp + d * 2);
            q2[d]     = mul2(pack2(t.x, t.y), scale2);
            q2[d + 1] = mul2(pack2(t.z, t.w), scale2);
        }
    }

    u64 O2[HD2];
    #pragma unroll
    for (int d = 0; d < HD2; d++) O2[d] = 0ull;
    float m = -1e30f, l = 0.f;

    const int nkt = (blockIdx.x * AT_ROWS + AT_ROWS) / AT_TK;  // causal tile count

    for (int kt = 0; kt < nkt; kt++) {
        const float* kbase = qkv + ((size_t)(b * SEQ + kt * AT_TK) * QKV_N) + CH + h * HD;
        #pragma unroll
        for (int it = 0; it < (AT_TK * HD / 4) / AT_ROWS; it++) {
            int idx = it * AT_ROWS + threadIdx.x;
            int j = idx / (HD / 4);
            int cc = (idx % (HD / 4)) * 4;
            const float* src = kbase + (size_t)j * QKV_N + cc;
            *(float4*)&Ks[j][cc] = *(const float4*)(src);
            *(float4*)&Vs[j][cc] = *(const float4*)(src + CH);
        }
        __syncthreads();

        const int jmax = min(AT_TK, qi - kt * AT_TK + 1);
        for (int j = 0; j < jmax; j++) {
            const u64* k2 = (const u64*)&Ks[j][0];
            u64 acc2 = 0ull;
            #pragma unroll
            for (int d = 0; d < HD2; d++) acc2 = fma2(q2[d], k2[d], acc2);
            float slo, shi; unpack2(acc2, slo, shi);
            float s = slo + shi;

            if (s > m) {
                float coef = __expf(m - s);
                l *= coef;
                const u64 coef2 = pack2(coef, coef);
                #pragma unroll
                for (int d = 0; d < HD2; d++) O2[d] = mul2(O2[d], coef2);
                m = s;
            }
            float p = __expf(s - m);
            l += p;
            const u64 p2 = pack2(p, p);
            const u64* v2 = (const u64*)&Vs[j][0];
            #pragma unroll
            for (int d = 0; d < HD2; d++) O2[d] = fma2(p2, v2[d], O2[d]);
        }
        __syncthreads();
    }

    const float inv = 1.f / l;
    float* yp = y + ((size_t)(b * SEQ + qi) * CH) + h * HD;
    #pragma unroll
    for (int d = 0; d < HD2; d += 2) {
        float4 o;
        unpack2(O2[d], o.x, o.y);
        unpack2(O2[d + 1], o.z, o.w);
        o.x *= inv; o.y *= inv; o.z *= inv; o.w *= inv;
        *(float4*)(yp + d * 2) = o;
    }
}

// ---------------- launch --------------------------------------------------
extern "C" void kernel_launch(void* const* d_in, const int* in_sizes, int n_in,
                              void* d_out, int out_size)
{
    const float* x      = (const float*)d_in[0];   // [B,T,C]
    const float* w_qkv  = (const float*)d_in[1];   // [C,3C]
    const float* b_qkv  = (const float*)d_in[2];   // [3C]
    const float* w_proj = (const float*)d_in[3];   // [C,C]
    const float* b_proj = (const float*)d_in[4];   // [C]
    float* out = (float*)d_out;

    float* qkv = nullptr;
    float* y   = nullptr;
    cudaGetSymbolAddress((void**)&qkv, g_qkv);
    cudaGetSymbolAddress((void**)&y,   g_y);

    // 1) QKV GEMM: [8192,1024] @ [1024,3072] + bias -> g_qkv
    {
        dim3 grid(QKV_N / GBN, M_ROWS / GBM);
        gemm_tf32<<<grid, 128>>>(x, w_qkv, b_qkv, qkv, M_ROWS, QKV_N, CH);
    }

    // 2) causal flash attention -> g_y
    {
        dim3 grid(SEQ / AT_ROWS, NH, BATCH);
        attn_kernel<<<grid, AT_ROWS>>>(qkv, y);
    }

    // 3) proj GEMM: [8192,1024] @ [1024,1024] + bias -> out
    {
        dim3 grid(CH / GBN, M_ROWS / GBM);
        gemm_tf32<<<grid, 128>>>(y, w_proj, b_proj, out, M_ROWS, CH, CH);
    }
}

// round 4
// speedup vs baseline: 4.2109x; 3.0301x over previous
#include <cuda_runtime.h>
#include <cuda_bf16.h>
#include <cstdint>
#include <math.h>

// Problem constants
#define BATCH 4
#define SEQ   2048
#define CH    1024
#define NH    16
#define HD    64
#define M_ROWS (BATCH*SEQ)          // 8192
#define QKV_N  (3*CH)               // 3072

// ---------------- scratch (device globals: allocation-guard safe) ----------
__device__ float g_qkv[(size_t)M_ROWS * QKV_N];   // [B*T, 3C] (tf32-rounded)
__device__ float g_y  [(size_t)M_ROWS * CH];      // [B*T, C]

// ---------------- common helpers ------------------------------------------
__device__ __forceinline__ unsigned f2tf32(float f) {
    unsigned u; asm("cvt.rna.tf32.f32 %0, %1;" : "=r"(u) : "f"(f)); return u;
}
__device__ __forceinline__ void mma_tf32(float c[4], const unsigned a[4], const unsigned b[2]) {
    asm volatile("mma.sync.aligned.m16n8k8.row.col.f32.tf32.tf32.f32 "
        "{%0,%1,%2,%3}, {%4,%5,%6,%7}, {%8,%9}, {%0,%1,%2,%3};"
        : "+f"(c[0]), "+f"(c[1]), "+f"(c[2]), "+f"(c[3])
        : "r"(a[0]), "r"(a[1]), "r"(a[2]), "r"(a[3]), "r"(b[0]), "r"(b[1]));
}
__device__ __forceinline__ void cp_async16(unsigned s, const void* g) {
    asm volatile("cp.async.ca.shared.global [%0], [%1], 16;" :: "r"(s), "l"(g));
}
__device__ __forceinline__ unsigned smem_u32(const void* p) {
    return (unsigned)__cvta_generic_to_shared(p);
}
__device__ __forceinline__ void ldsm_x4(unsigned& r0, unsigned& r1, unsigned& r2, unsigned& r3,
                                        unsigned addr) {
    asm volatile("ldmatrix.sync.aligned.m8n8.x4.shared.b16 {%0,%1,%2,%3}, [%4];"
        : "=r"(r0), "=r"(r1), "=r"(r2), "=r"(r3) : "r"(addr));
}

// ======================= tf32 tensor-core GEMM ============================
// C[M,N] = A[M,K] @ B[K,N] + bias. Block 128x128x16, 8 warps, warp tile 64x32.
#define GBM 128
#define GBN 128
#define GBK 16
#define AST 20     // A smem stride (16 + 4 pad): 80B rows, LDSM conflict-free
#define BST 136    // B smem stride (128 + 8 pad): scalar B-frag conflict-free

__global__ __launch_bounds__(256, 2)
void gemm_tf32(const float* __restrict__ A, const float* __restrict__ B,
               const float* __restrict__ bias, float* __restrict__ C,
               int M, int N, int K, int cvt_out)
{
    __shared__ __align__(16) float As[2][GBM][AST];   // [m][k]
    __shared__ __align__(16) float Bs[2][GBK][BST];   // [k][n]

    const int tid  = threadIdx.x;
    const int lane = tid & 31;
    const int warp = tid >> 5;
    const int wm = warp >> 2;           // 0..1  (64 rows)
    const int wn = warp & 3;            // 0..3  (32 cols)
    const int bx = blockIdx.x, by = blockIdx.y;

    float acc[4][4][4];
    #pragma unroll
    for (int i = 0; i < 4; i++)
        #pragma unroll
        for (int j = 0; j < 4; j++)
            #pragma unroll
            for (int t = 0; t < 4; t++) acc[i][j][t] = 0.f;

    // gmem->smem staging (256 threads, 2 float4 each per tile)
    const int arow = tid >> 2, acol = (tid & 3) << 2;      // A: 128x16
    const int brow = tid >> 5, bcol = (tid & 31) << 2;     // B: 16x128
    const float* Aptr = A + (size_t)(by * GBM + arow) * K + acol;
    const float* Bptr = B + (size_t)brow * N + (size_t)bx * GBN + bcol;

    const int NKT = K / GBK;

    // prologue: stage 0
    cp_async16(smem_u32(&As[0][arow][acol]),      Aptr);
    cp_async16(smem_u32(&As[0][arow + 64][acol]), Aptr + (size_t)64 * K);
    cp_async16(smem_u32(&Bs[0][brow][bcol]),      Bptr);
    cp_async16(smem_u32(&Bs[0][brow + 8][bcol]),  Bptr + (size_t)8 * N);
    asm volatile("cp.async.commit_group;");

    for (int kt = 0; kt < NKT; kt++) {
        const int buf = kt & 1;
        if (kt + 1 < NKT) {
            const int k0 = (kt + 1) * GBK;
            cp_async16(smem_u32(&As[buf ^ 1][arow][acol]),      Aptr + k0);
            cp_async16(smem_u32(&As[buf ^ 1][arow + 64][acol]), Aptr + (size_t)64 * K + k0);
            cp_async16(smem_u32(&Bs[buf ^ 1][brow][bcol]),      Bptr + (size_t)k0 * N);
            cp_async16(smem_u32(&Bs[buf ^ 1][brow + 8][bcol]),  Bptr + (size_t)(k0 + 8) * N);
            asm volatile("cp.async.commit_group;");
            asm volatile("cp.async.wait_group 1;");
        } else {
            asm volatile("cp.async.wait_group 0;");
        }
        __syncthreads();

        #pragma unroll
        for (int ks = 0; ks < 2; ks++) {
            unsigned a[4][4], b[4][2];
            const int kk = ks * 8 + (lane & 3);
            #pragma unroll
            for (int mf = 0; mf < 4; mf++) {
                unsigned ad = smem_u32(&As[buf][wm * 64 + mf * 16 + (lane & 15)]
                                          [ks * 8 + ((lane >> 4) << 2)]);
                ldsm_x4(a[mf][0], a[mf][1], a[mf][2], a[mf][3], ad);
                #pragma unroll
                for (int i = 0; i < 4; i++)
                    a[mf][i] = f2tf32(__uint_as_float(a[mf][i]));
            }
            #pragma unroll
            for (int nf = 0; nf < 4; nf++) {
                const int n = wn * 32 + nf * 8 + (lane >> 2);
                b[nf][0] = f2tf32(Bs[buf][kk][n]);
                b[nf][1] = f2tf32(Bs[buf][kk + 4][n]);
            }
            #pragma unroll
            for (int mf = 0; mf < 4; mf++)
                #pragma unroll
                for (int nf = 0; nf < 4; nf++)
                    mma_tf32(acc[mf][nf], a[mf], b[nf]);
        }
        __syncthreads();
    }

    // epilogue: bias + (optional tf32 rounding) + store
    const int r0  = lane >> 2;
    const int c0l = (lane & 3) * 2;
    #pragma unroll
    for (int mf = 0; mf < 4; mf++) {
        const int row = by * GBM + wm * 64 + mf * 16 + r0;
        #pragma unroll
        for (int nf = 0; nf < 4; nf++) {
            const int col = bx * GBN + wn * 32 + nf * 8 + c0l;
            const float2 bb = *(const float2*)&bias[col];
            float v00 = acc[mf][nf][0] + bb.x, v01 = acc[mf][nf][1] + bb.y;
            float v10 = acc[mf][nf][2] + bb.x, v11 = acc[mf][nf][3] + bb.y;
            if (cvt_out) {
                v00 = __uint_as_float(f2tf32(v00)); v01 = __uint_as_float(f2tf32(v01));
                v10 = __uint_as_float(f2tf32(v10)); v11 = __uint_as_float(f2tf32(v11));
            }
            *(float2*)(C + (size_t)row * N + col)       = make_float2(v00, v01);
            *(float2*)(C + (size_t)(row + 8) * N + col) = make_float2(v10, v11);
        }
    }
}

// ============== Flash attention, tf32 mma.sync, 64 q-rows/block =============
// 4 warps x 16 q-rows. Q frags register-resident. K/V tiles 64x64 in smem.
#define AKS 68   // Ks stride (floats): conflict-free LDSM + scalar
#define AVS 72   // Vs stride: conflict-free scalar B-frag reads
#define APS 68   // per-warp P stride

#define ATTN_SMEM ((64*AKS + 64*AVS + 4*16*APS) * 4)   // 53248 B

__global__ __launch_bounds__(128, 3)
void attn_mma(const float* __restrict__ qkv, float* __restrict__ y)
{
    extern __shared__ float sm[];
    float* Ks = sm;                        // [64][AKS]  (also Q staging)
    float* Vs = sm + 64 * AKS;             // [64][AVS]  raw [key][d]
    float* Ps = sm + 64 * AKS + 64 * AVS;  // [4][16][APS]

    const int b = blockIdx.z, h = blockIdx.y;
    const int qt = gridDim.x - 1 - blockIdx.x;    // heavy blocks first
    const int tid = threadIdx.x, lane = tid & 31, warp = tid >> 5;
    const int g = lane >> 2, cq = lane & 3;
    const int qbase = qt * 64;

    // ---- stage Q tile into Ks, build register-resident Q frags ----
    #pragma unroll
    for (int i = 0; i < 8; i++) {
        int chunk = i * 128 + tid;
        int row = chunk >> 4, col = (chunk & 15) << 2;
        cp_async16(smem_u32(&Ks[row * AKS + col]),
                   qkv + (size_t)(b * SEQ + qbase + row) * QKV_N + h * HD + col);
    }
    asm volatile("cp.async.commit_group;");
    asm volatile("cp.async.wait_group 0;");
    __syncthreads();

    unsigned qf[8][4];
    {
        const int qrow = warp * 16 + (lane & 15);
        const int qcol = (lane >> 4) << 2;
        #pragma unroll
        for (int ks = 0; ks < 8; ks++) {
            ldsm_x4(qf[ks][0], qf[ks][1], qf[ks][2], qf[ks][3],
                    smem_u32(&Ks[qrow * AKS + ks * 8 + qcol]));
            #pragma unroll
            for (int i = 0; i < 4; i++)   // fold softmax scale (exact: 2^-3)
                qf[ks][i] = __float_as_uint(__uint_as_float(qf[ks][i]) * 0.125f);
        }
    }

    float o[8][4];
    #pragma unroll
    for (int nf = 0; nf < 8; nf++)
        #pragma unroll
        for (int j = 0; j < 4; j++) o[nf][j] = 0.f;
    float m0 = -1e30f, m1 = -1e30f, l0 = 0.f, l1 = 0.f;

    // ldmatrix lane->address components
    const int krow_off = (lane & 7) + ((lane >> 4) & 1) * 8;  // K/V b-frag rows
    const int kcol_off = ((lane >> 3) & 1) * 4;
    const int prow = lane & 15;                                // P a-frag rows
    const int pcol = (lane >> 4) << 2;
    float* myP = Ps + warp * 16 * APS;

    for (int kt = 0; kt <= qt; kt++) {
        __syncthreads();   // all warps done reading Ks/Vs (and Q staging)
        #pragma unroll
        for (int i = 0; i < 8; i++) {
            int chunk = i * 128 + tid;
            int row = chunk >> 4, col = (chunk & 15) << 2;
            const float* src = qkv + (size_t)(b * SEQ + kt * 64 + row) * QKV_N
                                   + CH + h * HD + col;
            cp_async16(smem_u32(&Ks[row * AKS + col]), src);        // K
            cp_async16(smem_u32(&Vs[row * AVS + col]), src + CH);   // V
        }
        asm volatile("cp.async.commit_group;");
        asm volatile("cp.async.wait_group 0;");
        __syncthreads();

        // ---- S = Q @ K^T (K already tf32-rounded in storage) ----
        float s[8][4];
        #pragma unroll
        for (int nf = 0; nf < 8; nf++)
            #pragma unroll
            for (int j = 0; j < 4; j++) s[nf][j] = 0.f;

        #pragma unroll
        for (int ks = 0; ks < 8; ks++) {
            unsigned bf[8][2];
            #pragma unroll
            for (int nfp = 0; nfp < 4; nfp++)
                ldsm_x4(bf[2*nfp][0], bf[2*nfp][1], bf[2*nfp+1][0], bf[2*nfp+1][1],
                        smem_u32(&Ks[(nfp * 16 + krow_off) * AKS + ks * 8 + kcol_off]));
            #pragma unroll
            for (int nf = 0; nf < 8; nf++)
                mma_tf32(s[nf], qf[ks], bf[nf]);
        }

        // ---- causal mask (diagonal tile only) ----
        if (kt == qt) {
            const int q0 = qbase + warp * 16 + g;
            const int kb = kt * 64 + 2 * cq;
            #pragma unroll
            for (int nf = 0; nf < 8; nf++) {
                const int k0 = kb + nf * 8;
                if (k0     > q0)     s[nf][0] = -1e30f;
                if (k0 + 1 > q0)     s[nf][1] = -1e30f;
                if (k0     > q0 + 8) s[nf][2] = -1e30f;
                if (k0 + 1 > q0 + 8) s[nf][3] = -1e30f;
            }
        }

        // ---- online softmax ----
        float mx0 = -1e30f, mx1 = -1e30f;
        #pragma unroll
        for (int nf = 0; nf < 8; nf++) {
            mx0 = fmaxf(mx0, fmaxf(s[nf][0], s[nf][1]));
            mx1 = fmaxf(mx1, fmaxf(s[nf][2], s[nf][3]));
        }
        mx0 = fmaxf(mx0, __shfl_xor_sync(0xffffffffu, mx0, 1));
        mx0 = fmaxf(mx0, __shfl_xor_sync(0xffffffffu, mx0, 2));
        mx1 = fmaxf(mx1, __shfl_xor_sync(0xffffffffu, mx1, 1));
        mx1 = fmaxf(mx1, __shfl_xor_sync(0xffffffffu, mx1, 2));
        const float mn0 = fmaxf(m0, mx0), mn1 = fmaxf(m1, mx1);
        const float coef0 = __expf(m0 - mn0), coef1 = __expf(m1 - mn1);
        m0 = mn0; m1 = mn1;

        float sum0 = 0.f, sum1 = 0.f;
        #pragma unroll
        for (int nf = 0; nf < 8; nf++) {
            s[nf][0] = __uint_as_float(f2tf32(__expf(s[nf][0] - m0)));
            s[nf][1] = __uint_as_float(f2tf32(__expf(s[nf][1] - m0)));
            s[nf][2] = __uint_as_float(f2tf32(__expf(s[nf][2] - m1)));
            s[nf][3] = __uint_as_float(f2tf32(__expf(s[nf][3] - m1)));
            sum0 += s[nf][0] + s[nf][1];
            sum1 += s[nf][2] + s[nf][3];
        }
        sum0 += __shfl_xor_sync(0xffffffffu, sum0, 1);
        sum0 += __shfl_xor_sync(0xffffffffu, sum0, 2);
        sum1 += __shfl_xor_sync(0xffffffffu, sum1, 1);
        sum1 += __shfl_xor_sync(0xffffffffu, sum1, 2);
        l0 = l0 * coef0 + sum0;
        l1 = l1 * coef1 + sum1;

        #pragma unroll
        for (int nf = 0; nf < 8; nf++) {
            o[nf][0] *= coef0; o[nf][1] *= coef0;
            o[nf][2] *= coef1; o[nf][3] *= coef1;
        }

        // ---- P: C-frag layout -> smem -> A-frag layout ----
        #pragma unroll
        for (int nf = 0; nf < 8; nf++) {
            *(float2*)&myP[g * APS + nf * 8 + 2 * cq]       = make_float2(s[nf][0], s[nf][1]);
            *(float2*)&myP[(g + 8) * APS + nf * 8 + 2 * cq] = make_float2(s[nf][2], s[nf][3]);
        }
        __syncwarp();

        // ---- O += P @ V (V tf32-rounded in storage) ----
        #pragma unroll
        for (int ks = 0; ks < 8; ks++) {
            unsigned ap[4];
            ldsm_x4(ap[0], ap[1], ap[2], ap[3],
                    smem_u32(&myP[prow * APS + ks * 8 + pcol]));
            #pragma unroll
            for (int nf = 0; nf < 8; nf++) {
                unsigned bv[2];
                bv[0] = __float_as_uint(Vs[(ks * 8 + cq) * AVS + nf * 8 + g]);
                bv[1] = __float_as_uint(Vs[(ks * 8 + 4 + cq) * AVS + nf * 8 + g]);
                mma_tf32(o[nf], ap, bv);
            }
        }
        __syncwarp();
    }

    // ---- epilogue ----
    const float inv0 = 1.f / l0, inv1 = 1.f / l1;
    const int row0 = qbase + warp * 16 + g;
    float* y0 = y + (size_t)(b * SEQ + row0) * CH + h * HD;
    float* y1 = y0 + (size_t)8 * CH;
    #pragma unroll
    for (int nf = 0; nf < 8; nf++) {
        const int col = nf * 8 + 2 * cq;
        *(float2*)&y0[col] = make_float2(o[nf][0] * inv0, o[nf][1] * inv0);
        *(float2*)&y1[col] = make_float2(o[nf][2] * inv1, o[nf][3] * inv1);
    }
}

// ---------------- launch --------------------------------------------------
extern "C" void kernel_launch(void* const* d_in, const int* in_sizes, int n_in,
                              void* d_out, int out_size)
{
    const float* x      = (const float*)d_in[0];   // [B,T,C]
    const float* w_qkv  = (const float*)d_in[1];   // [C,3C]
    const float* b_qkv  = (const float*)d_in[2];   // [3C]
    const float* w_proj = (const float*)d_in[3];   // [C,C]
    const float* b_proj = (const float*)d_in[4];   // [C]
    float* out = (float*)d_out;

    float* qkv = nullptr;
    float* y   = nullptr;
    cudaGetSymbolAddress((void**)&qkv, g_qkv);
    cudaGetSymbolAddress((void**)&y,   g_y);

    cudaFuncSetAttribute(attn_mma, cudaFuncAttributeMaxDynamicSharedMemorySize,
                         ATTN_SMEM);

    // 1) QKV GEMM (+tf32 rounding of outputs): [8192,1024]@[1024,3072] -> g_qkv
    {
        dim3 grid(QKV_N / GBN, M_ROWS / GBM);
        gemm_tf32<<<grid, 256>>>(x, w_qkv, b_qkv, qkv, M_ROWS, QKV_N, CH, 1);
    }

    // 2) causal flash attention (tensor cores) -> g_y
    {
        dim3 grid(SEQ / 64, NH, BATCH);
        attn_mma<<<grid, 128, ATTN_SMEM>>>(qkv, y);
    }

    // 3) proj GEMM: [8192,1024]@[1024,1024] -> out
    {
        dim3 grid(CH / GBN, M_ROWS / GBM);
        gemm_tf32<<<grid, 256>>>(y, w_proj, b_proj, out, M_ROWS, CH, CH, 0);
    }
}

// round 5
// speedup vs baseline: 4.3069x; 1.0228x over previous
#include <cuda_runtime.h>
#include <cuda_bf16.h>
#include <cstdint>
#include <math.h>

// Problem constants
#define BATCH 4
#define SEQ   2048
#define CH    1024
#define NH    16
#define HD    64
#define M_ROWS (BATCH*SEQ)          // 8192
#define QKV_N  (3*CH)               // 3072

// ---------------- scratch (device globals: allocation-guard safe) ----------
__device__ float g_qkv  [(size_t)M_ROWS * QKV_N];   // [B*T, 3C] (tf32-rounded)
__device__ float g_y    [(size_t)M_ROWS * CH];      // [B*T, C]  (tf32-rounded)
__device__ float g_xr   [(size_t)M_ROWS * CH];      // tf32-rounded x
__device__ float g_wqkv [(size_t)CH * QKV_N];       // tf32-rounded w_qkv
__device__ float g_wproj[(size_t)CH * CH];          // tf32-rounded w_proj

// ---------------- common helpers ------------------------------------------
__device__ __forceinline__ unsigned f2tf32(float f) {
    unsigned u; asm("cvt.rna.tf32.f32 %0, %1;" : "=r"(u) : "f"(f)); return u;
}
__device__ __forceinline__ float rnd_tf32(float f) {
    return __uint_as_float(f2tf32(f));
}
__device__ __forceinline__ void mma_tf32(float c[4], const unsigned a[4], const unsigned b[2]) {
    asm volatile("mma.sync.aligned.m16n8k8.row.col.f32.tf32.tf32.f32 "
        "{%0,%1,%2,%3}, {%4,%5,%6,%7}, {%8,%9}, {%0,%1,%2,%3};"
        : "+f"(c[0]), "+f"(c[1]), "+f"(c[2]), "+f"(c[3])
        : "r"(a[0]), "r"(a[1]), "r"(a[2]), "r"(a[3]), "r"(b[0]), "r"(b[1]));
}
__device__ __forceinline__ void cp_async16(unsigned s, const void* g) {
    asm volatile("cp.async.ca.shared.global [%0], [%1], 16;" :: "r"(s), "l"(g));
}
__device__ __forceinline__ unsigned smem_u32(const void* p) {
    return (unsigned)__cvta_generic_to_shared(p);
}
__device__ __forceinline__ void ldsm_x4(unsigned& r0, unsigned& r1, unsigned& r2, unsigned& r3,
                                        unsigned addr) {
    asm volatile("ldmatrix.sync.aligned.m8n8.x4.shared.b16 {%0,%1,%2,%3}, [%4];"
        : "=r"(r0), "=r"(r1), "=r"(r2), "=r"(r3) : "r"(addr));
}

// ---------------- elementwise tf32 pre-rounding ----------------------------
__global__ void round_tf32_kernel(const float* __restrict__ in,
                                  float* __restrict__ out, int n4)
{
    int i = blockIdx.x * blockDim.x + threadIdx.x;
    if (i < n4) {
        float4 v = ((const float4*)in)[i];
        v.x = rnd_tf32(v.x); v.y = rnd_tf32(v.y);
        v.z = rnd_tf32(v.z); v.w = rnd_tf32(v.w);
        ((float4*)out)[i] = v;
    }
}

// ======================= tf32 tensor-core GEMM ============================
// C[M,N] = A[M,K] @ B[K,N] + bias. A,B pre-rounded to tf32. Block 128x128x16,
// 8 warps, warp tile 64x32, cp.async double-buffered. No cvt in hot loop.
#define GBM 128
#define GBN 128
#define GBK 16
#define AST 20     // A smem stride (16 + 4 pad)
#define BST 136    // B smem stride (128 + 8 pad)

__global__ __launch_bounds__(256, 2)
void gemm_tf32(const float* __restrict__ A, const float* __restrict__ B,
               const float* __restrict__ bias, float* __restrict__ C,
               int M, int N, int K, int cvt_out)
{
    __shared__ __align__(16) float As[2][GBM][AST];   // [m][k]
    __shared__ __align__(16) float Bs[2][GBK][BST];   // [k][n]

    const int tid  = threadIdx.x;
    const int lane = tid & 31;
    const int warp = tid >> 5;
    const int wm = warp >> 2;           // 0..1
    const int wn = warp & 3;            // 0..3
    const int bx = blockIdx.x, by = blockIdx.y;

    float acc[4][4][4];
    #pragma unroll
    for (int i = 0; i < 4; i++)
        #pragma unroll
        for (int j = 0; j < 4; j++)
            #pragma unroll
            for (int t = 0; t < 4; t++) acc[i][j][t] = 0.f;

    const int arow = tid >> 2, acol = (tid & 3) << 2;      // A: 128x16
    const int brow = tid >> 5, bcol = (tid & 31) << 2;     // B: 16x128
    const float* Aptr = A + (size_t)(by * GBM + arow) * K + acol;
    const float* Bptr = B + (size_t)brow * N + (size_t)bx * GBN + bcol;

    const int NKT = K / GBK;

    cp_async16(smem_u32(&As[0][arow][acol]),      Aptr);
    cp_async16(smem_u32(&As[0][arow + 64][acol]), Aptr + (size_t)64 * K);
    cp_async16(smem_u32(&Bs[0][brow][bcol]),      Bptr);
    cp_async16(smem_u32(&Bs[0][brow + 8][bcol]),  Bptr + (size_t)8 * N);
    asm volatile("cp.async.commit_group;");

    for (int kt = 0; kt < NKT; kt++) {
        const int buf = kt & 1;
        if (kt + 1 < NKT) {
            const int k0 = (kt + 1) * GBK;
            cp_async16(smem_u32(&As[buf ^ 1][arow][acol]),      Aptr + k0);
            cp_async16(smem_u32(&As[buf ^ 1][arow + 64][acol]), Aptr + (size_t)64 * K + k0);
            cp_async16(smem_u32(&Bs[buf ^ 1][brow][bcol]),      Bptr + (size_t)k0 * N);
            cp_async16(smem_u32(&Bs[buf ^ 1][brow + 8][bcol]),  Bptr + (size_t)(k0 + 8) * N);
            asm volatile("cp.async.commit_group;");
            asm volatile("cp.async.wait_group 1;");
        } else {
            asm volatile("cp.async.wait_group 0;");
        }
        __syncthreads();

        #pragma unroll
        for (int ks = 0; ks < 2; ks++) {
            unsigned a[4][4], b[4][2];
            const int kk = ks * 8 + (lane & 3);
            #pragma unroll
            for (int mf = 0; mf < 4; mf++) {
                unsigned ad = smem_u32(&As[buf][wm * 64 + mf * 16 + (lane & 15)]
                                          [ks * 8 + ((lane >> 4) << 2)]);
                ldsm_x4(a[mf][0], a[mf][1], a[mf][2], a[mf][3], ad);
            }
            #pragma unroll
            for (int nf = 0; nf < 4; nf++) {
                const int n = wn * 32 + nf * 8 + (lane >> 2);
                b[nf][0] = __float_as_uint(Bs[buf][kk][n]);
                b[nf][1] = __float_as_uint(Bs[buf][kk + 4][n]);
            }
            #pragma unroll
            for (int mf = 0; mf < 4; mf++)
                #pragma unroll
                for (int nf = 0; nf < 4; nf++)
                    mma_tf32(acc[mf][nf], a[mf], b[nf]);
        }
        __syncthreads();
    }

    const int r0  = lane >> 2;
    const int c0l = (lane & 3) * 2;
    #pragma unroll
    for (int mf = 0; mf < 4; mf++) {
        const int row = by * GBM + wm * 64 + mf * 16 + r0;
        #pragma unroll
        for (int nf = 0; nf < 4; nf++) {
            const int col = bx * GBN + wn * 32 + nf * 8 + c0l;
            const float2 bb = *(const float2*)&bias[col];
            float v00 = acc[mf][nf][0] + bb.x, v01 = acc[mf][nf][1] + bb.y;
            float v10 = acc[mf][nf][2] + bb.x, v11 = acc[mf][nf][3] + bb.y;
            if (cvt_out) {
                v00 = rnd_tf32(v00); v01 = rnd_tf32(v01);
                v10 = rnd_tf32(v10); v11 = rnd_tf32(v11);
            }
            *(float2*)(C + (size_t)row * N + col)       = make_float2(v00, v01);
            *(float2*)(C + (size_t)(row + 8) * N + col) = make_float2(v10, v11);
        }
    }
}

// ============== Flash attention, tf32 mma.sync, double-buffered K/V ========
// 4 warps x 16 q-rows = 64 q-rows/block. K/V tiles 64x64, 2-stage cp.async.
#define AKS 68
#define AVS 72
#define APS 68
#define ATTN_SMEM ((2*64*AKS + 2*64*AVS + 4*16*APS) * 4)   // 89088 B

__global__ __launch_bounds__(128, 2)
void attn_mma(const float* __restrict__ qkv, float* __restrict__ y)
{
    extern __shared__ float sm[];
    float* Ks = sm;                                   // [2][64][AKS]
    float* Vs = sm + 2 * 64 * AKS;                    // [2][64][AVS]
    float* Ps = sm + 2 * 64 * AKS + 2 * 64 * AVS;     // [4][16][APS] (+Q staging)

    const int b = blockIdx.z, h = blockIdx.y;
    const int qt = gridDim.x - 1 - blockIdx.x;        // heavy blocks first
    const int tid = threadIdx.x, lane = tid & 31, warp = tid >> 5;
    const int g = lane >> 2, cq = lane & 3;
    const int qbase = qt * 64;

    // ---- stage Q tile into Ps (as [64][APS]), build register Q frags ----
    #pragma unroll
    for (int i = 0; i < 8; i++) {
        int chunk = i * 128 + tid;
        int row = chunk >> 4, col = (chunk & 15) << 2;
        cp_async16(smem_u32(&Ps[row * APS + col]),
                   qkv + (size_t)(b * SEQ + qbase + row) * QKV_N + h * HD + col);
    }
    asm volatile("cp.async.commit_group;");
    asm volatile("cp.async.wait_group 0;");
    __syncthreads();

    unsigned qf[8][4];
    {
        const int qrow = warp * 16 + (lane & 15);
        const int qcol = (lane >> 4) << 2;
        #pragma unroll
        for (int ks = 0; ks < 8; ks++) {
            ldsm_x4(qf[ks][0], qf[ks][1], qf[ks][2], qf[ks][3],
                    smem_u32(&Ps[qrow * APS + ks * 8 + qcol]));
            #pragma unroll
            for (int i = 0; i < 4; i++)   // fold softmax scale (exact: 2^-3)
                qf[ks][i] = __float_as_uint(__uint_as_float(qf[ks][i]) * 0.125f);
        }
    }
    // Each warp read only its own Ps region and writes only its own region
    // later (program order within warp) -> no extra sync needed.

    float o[8][4];
    #pragma unroll
    for (int nf = 0; nf < 8; nf++)
        #pragma unroll
        for (int j = 0; j < 4; j++) o[nf][j] = 0.f;
    float m0 = -1e30f, m1 = -1e30f, l0 = 0.f, l1 = 0.f;

    const int krow_off = (lane & 7) + ((lane >> 4) & 1) * 8;
    const int kcol_off = ((lane >> 3) & 1) * 4;
    const int prow = lane & 15;
    const int pcol = (lane >> 4) << 2;
    float* myP = Ps + warp * 16 * APS;

    // K/V tile loader
    auto kv_load = [&](int buf, int kt) {
        #pragma unroll
        for (int i = 0; i < 8; i++) {
            int chunk = i * 128 + tid;
            int row = chunk >> 4, col = (chunk & 15) << 2;
            const float* src = qkv + (size_t)(b * SEQ + kt * 64 + row) * QKV_N
                                   + CH + h * HD + col;
            cp_async16(smem_u32(&Ks[buf * 64 * AKS + row * AKS + col]), src);
            cp_async16(smem_u32(&Vs[buf * 64 * AVS + row * AVS + col]), src + CH);
        }
        asm volatile("cp.async.commit_group;");
    };

    kv_load(0, 0);   // prologue

    for (int kt = 0; kt <= qt; kt++) {
        const int buf = kt & 1;
        asm volatile("cp.async.wait_group 0;");
        __syncthreads();
        if (kt < qt) kv_load(buf ^ 1, kt + 1);   // prefetch overlaps compute

        const float* Kb = Ks + buf * 64 * AKS;
        const float* Vb = Vs + buf * 64 * AVS;

        // ---- S = Q @ K^T ----
        float s[8][4];
        #pragma unroll
        for (int nf = 0; nf < 8; nf++)
            #pragma unroll
            for (int j = 0; j < 4; j++) s[nf][j] = 0.f;

        #pragma unroll
        for (int ks = 0; ks < 8; ks++) {
            unsigned bf[8][2];
            #pragma unroll
            for (int nfp = 0; nfp < 4; nfp++)
                ldsm_x4(bf[2*nfp][0], bf[2*nfp][1], bf[2*nfp+1][0], bf[2*nfp+1][1],
                        smem_u32(&Kb[(nfp * 16 + krow_off) * AKS + ks * 8 + kcol_off]));
            #pragma unroll
            for (int nf = 0; nf < 8; nf++)
                mma_tf32(s[nf], qf[ks], bf[nf]);
        }

        // ---- causal mask (diagonal tile only) ----
        if (kt == qt) {
            const int q0 = qbase + warp * 16 + g;
            const int kb = kt * 64 + 2 * cq;
            #pragma unroll
            for (int nf = 0; nf < 8; nf++) {
                const int k0 = kb + nf * 8;
                if (k0     > q0)     s[nf][0] = -1e30f;
                if (k0 + 1 > q0)     s[nf][1] = -1e30f;
                if (k0     > q0 + 8) s[nf][2] = -1e30f;
                if (k0 + 1 > q0 + 8) s[nf][3] = -1e30f;
            }
        }

        // ---- online softmax ----
        float mx0 = -1e30f, mx1 = -1e30f;
        #pragma unroll
        for (int nf = 0; nf < 8; nf++) {
            mx0 = fmaxf(mx0, fmaxf(s[nf][0], s[nf][1]));
            mx1 = fmaxf(mx1, fmaxf(s[nf][2], s[nf][3]));
        }
        mx0 = fmaxf(mx0, __shfl_xor_sync(0xffffffffu, mx0, 1));
        mx0 = fmaxf(mx0, __shfl_xor_sync(0xffffffffu, mx0, 2));
        mx1 = fmaxf(mx1, __shfl_xor_sync(0xffffffffu, mx1, 1));
        mx1 = fmaxf(mx1, __shfl_xor_sync(0xffffffffu, mx1, 2));
        const float mn0 = fmaxf(m0, mx0), mn1 = fmaxf(m1, mx1);
        const float coef0 = __expf(m0 - mn0), coef1 = __expf(m1 - mn1);
        m0 = mn0; m1 = mn1;

        float sum0 = 0.f, sum1 = 0.f;
        #pragma unroll
        for (int nf = 0; nf < 8; nf++) {
            s[nf][0] = rnd_tf32(__expf(s[nf][0] - m0));
            s[nf][1] = rnd_tf32(__expf(s[nf][1] - m0));
            s[nf][2] = rnd_tf32(__expf(s[nf][2] - m1));
            s[nf][3] = rnd_tf32(__expf(s[nf][3] - m1));
            sum0 += s[nf][0] + s[nf][1];
            sum1 += s[nf][2] + s[nf][3];
        }
        sum0 += __shfl_xor_sync(0xffffffffu, sum0, 1);
        sum0 += __shfl_xor_sync(0xffffffffu, sum0, 2);
        sum1 += __shfl_xor_sync(0xffffffffu, sum1, 1);
        sum1 += __shfl_xor_sync(0xffffffffu, sum1, 2);
        l0 = l0 * coef0 + sum0;
        l1 = l1 * coef1 + sum1;

        #pragma unroll
        for (int nf = 0; nf < 8; nf++) {
            o[nf][0] *= coef0; o[nf][1] *= coef0;
            o[nf][2] *= coef1; o[nf][3] *= coef1;
        }

        // ---- P: C-frag -> smem -> A-frag ----
        #pragma unroll
        for (int nf = 0; nf < 8; nf++) {
            *(float2*)&myP[g * APS + nf * 8 + 2 * cq]       = make_float2(s[nf][0], s[nf][1]);
            *(float2*)&myP[(g + 8) * APS + nf * 8 + 2 * cq] = make_float2(s[nf][2], s[nf][3]);
        }
        __syncwarp();

        // ---- O += P @ V ----
        #pragma unroll
        for (int ks = 0; ks < 8; ks++) {
            unsigned ap[4];
            ldsm_x4(ap[0], ap[1], ap[2], ap[3],
                    smem_u32(&myP[prow * APS + ks * 8 + pcol]));
            #pragma unroll
            for (int nf = 0; nf < 8; nf++) {
                unsigned bv[2];
                bv[0] = __float_as_uint(Vb[(ks * 8 + cq) * AVS + nf * 8 + g]);
                bv[1] = __float_as_uint(Vb[(ks * 8 + 4 + cq) * AVS + nf * 8 + g]);
                mma_tf32(o[nf], ap, bv);
            }
        }
        __syncwarp();
    }

    // ---- epilogue (tf32-rounded so proj consumes without cvt) ----
    const float inv0 = 1.f / l0, inv1 = 1.f / l1;
    const int row0 = qbase + warp * 16 + g;
    float* y0 = y + (size_t)(b * SEQ + row0) * CH + h * HD;
    float* y1 = y0 + (size_t)8 * CH;
    #pragma unroll
    for (int nf = 0; nf < 8; nf++) {
        const int col = nf * 8 + 2 * cq;
        *(float2*)&y0[col] = make_float2(rnd_tf32(o[nf][0] * inv0), rnd_tf32(o[nf][1] * inv0));
        *(float2*)&y1[col] = make_float2(rnd_tf32(o[nf][2] * inv1), rnd_tf32(o[nf][3] * inv1));
    }
}

// ---------------- launch --------------------------------------------------
extern "C" void kernel_launch(void* const* d_in, const int* in_sizes, int n_in,
                              void* d_out, int out_size)
{
    const float* x      = (const float*)d_in[0];
    const float* w_qkv  = (const float*)d_in[1];
    const float* b_qkv  = (const float*)d_in[2];
    const float* w_proj = (const float*)d_in[3];
    const float* b_proj = (const float*)d_in[4];
    float* out = (float*)d_out;

    float *qkv, *y, *xr, *wqkvr, *wprojr;
    cudaGetSymbolAddress((void**)&qkv,    g_qkv);
    cudaGetSymbolAddress((void**)&y,      g_y);
    cudaGetSymbolAddress((void**)&xr,     g_xr);
    cudaGetSymbolAddress((void**)&wqkvr,  g_wqkv);
    cudaGetSymbolAddress((void**)&wprojr, g_wproj);

    cudaFuncSetAttribute(attn_mma, cudaFuncAttributeMaxDynamicSharedMemorySize,
                         ATTN_SMEM);

    // 0) pre-round inputs to tf32
    {
        int n;
        n = M_ROWS * CH / 4;
        round_tf32_kernel<<<(n + 255) / 256, 256>>>(x, xr, n);
        n = CH * QKV_N / 4;
        round_tf32_kernel<<<(n + 255) / 256, 256>>>(w_qkv, wqkvr, n);
        n = CH * CH / 4;
        round_tf32_kernel<<<(n + 255) / 256, 256>>>(w_proj, wprojr, n);
    }

    // 1) QKV GEMM (+tf32 rounding of outputs)
    {
        dim3 grid(QKV_N / GBN, M_ROWS / GBM);
        gemm_tf32<<<grid, 256>>>(xr, wqkvr, b_qkv, qkv, M_ROWS, QKV_N, CH, 1);
    }

    // 2) causal flash attention (tensor cores, double-buffered)
    {
        dim3 grid(SEQ / 64, NH, BATCH);
        attn_mma<<<grid, 128, ATTN_SMEM>>>(qkv, y);
    }

    // 3) proj GEMM
    {
        dim3 grid(CH / GBN, M_ROWS / GBM);
        gemm_tf32<<<grid, 256>>>(y, wprojr, b_proj, out, M_ROWS, CH, CH, 0);
    }
}

// round 7
// speedup vs baseline: 5.0854x; 1.1807x over previous
#include <cuda_runtime.h>
#include <cuda_bf16.h>
#include <cstdint>
#include <math.h>

// Problem constants
#define BATCH 4
#define SEQ   2048
#define CH    1024
#define NH    16
#define HD    64
#define M_ROWS (BATCH*SEQ)          // 8192
#define QKV_N  (3*CH)               // 3072

// ---------------- scratch (device globals: allocation-guard safe) ----------
__device__ float g_qkv  [(size_t)M_ROWS * QKV_N];   // [B*T, 3C] (tf32-rounded)
__device__ float g_y    [(size_t)M_ROWS * CH];      // [B*T, C]  (tf32-rounded)
__device__ float g_xr   [(size_t)M_ROWS * CH];      // tf32-rounded x
__device__ float g_wqkv [(size_t)CH * QKV_N];       // tf32-rounded w_qkv [K,N]
__device__ float g_wproj[(size_t)CH * CH];          // tf32-rounded w_proj [K,N]

// ---------------- common helpers ------------------------------------------
__device__ __forceinline__ unsigned f2tf32(float f) {
    unsigned u; asm("cvt.rna.tf32.f32 %0, %1;" : "=r"(u) : "f"(f)); return u;
}
__device__ __forceinline__ float rnd_tf32(float f) {
    return __uint_as_float(f2tf32(f));
}
__device__ __forceinline__ void mma_tf32(float c[4], const unsigned a[4], const unsigned b[2]) {
    asm volatile("mma.sync.aligned.m16n8k8.row.col.f32.tf32.tf32.f32 "
        "{%0,%1,%2,%3}, {%4,%5,%6,%7}, {%8,%9}, {%0,%1,%2,%3};"
        : "+f"(c[0]), "+f"(c[1]), "+f"(c[2]), "+f"(c[3])
        : "r"(a[0]), "r"(a[1]), "r"(a[2]), "r"(a[3]), "r"(b[0]), "r"(b[1]));
}
__device__ __forceinline__ void cp_async16(unsigned s, const void* g) {
    asm volatile("cp.async.cg.shared.global [%0], [%1], 16;" :: "r"(s), "l"(g));
}
__device__ __forceinline__ unsigned smem_u32(const void* p) {
    return (unsigned)__cvta_generic_to_shared(p);
}
__device__ __forceinline__ void ldsm_x4(unsigned& r0, unsigned& r1, unsigned& r2, unsigned& r3,
                                        unsigned addr) {
    asm volatile("ldmatrix.sync.aligned.m8n8.x4.shared.b16 {%0,%1,%2,%3}, [%4];"
        : "=r"(r0), "=r"(r1), "=r"(r2), "=r"(r3) : "r"(addr));
}

// ---------------- prep: elementwise tf32 rounding ---------------------------
__global__ void round_tf32_kernel(const float* __restrict__ in,
                                  float* __restrict__ out, int n4)
{
    int i = blockIdx.x * blockDim.x + threadIdx.x;
    if (i < n4) {
        float4 v = ((const float4*)in)[i];
        v.x = rnd_tf32(v.x); v.y = rnd_tf32(v.y);
        v.z = rnd_tf32(v.z); v.w = rnd_tf32(v.w);
        ((float4*)out)[i] = v;
    }
}

// ======================= tf32 mma.sync GEMM ================================
// C[M,N] = A[M,K] @ B[K,N] + bias. 4 warps, CTA 128x128x16, warp tile 64x64,
// 3-stage cp.async pipeline. A,B pre-rounded to tf32 (no cvt in hot loop).
#define GBM 128
#define GBN 128
#define GBK 16
#define AST 20     // A smem stride
#define BST 136    // B smem stride
#define A_FLOATS (GBM * AST)   // 2560
#define B_FLOATS (GBK * BST)   // 2176
#define GSTAGE (A_FLOATS + B_FLOATS)
#define GEMM_SMEM (3 * GSTAGE * 4)   // 56832 B

__global__ __launch_bounds__(128, 2)
void gemm_tf32(const float* __restrict__ A, const float* __restrict__ B,
               const float* __restrict__ bias, float* __restrict__ C,
               int M, int N, int K, int cvt_out)
{
    extern __shared__ float gsm[];
    // As(s,m,k) = gsm[s*GSTAGE + m*AST + k]
    // Bs(s,k,n) = gsm[s*GSTAGE + A_FLOATS + k*BST + n]

    const int tid  = threadIdx.x;
    const int lane = tid & 31;
    const int warp = tid >> 5;
    const int wm = warp >> 1;           // 0..1 (64 rows)
    const int wn = warp & 1;            // 0..1 (64 cols)
    const int bx = blockIdx.x, by = blockIdx.y;

    float acc[4][8][4];
    #pragma unroll
    for (int i = 0; i < 4; i++)
        #pragma unroll
        for (int j = 0; j < 8; j++)
            #pragma unroll
            for (int t = 0; t < 4; t++) acc[i][j][t] = 0.f;

    // staging: 128 threads, 4 float4 each for A and B
    const int arow = tid >> 2, acol = (tid & 3) << 2;      // A: rows tid>>2 (+32 steps)
    const int brow = tid >> 5, bcol = (tid & 31) << 2;     // B: rows tid>>5 (+4 steps)
    const float* Aptr = A + (size_t)(by * GBM + arow) * K + acol;
    const float* Bptr = B + (size_t)brow * N + (size_t)bx * GBN + bcol;

    const int NKT = K / GBK;

    auto load_stage = [&](int t, int s) {
        float* As = gsm + s * GSTAGE;
        float* Bs = gsm + s * GSTAGE + A_FLOATS;
        const int k0 = t * GBK;
        #pragma unroll
        for (int i = 0; i < 4; i++)
            cp_async16(smem_u32(&As[(arow + i * 32) * AST + acol]),
                       Aptr + (size_t)(i * 32) * K + k0);
        #pragma unroll
        for (int i = 0; i < 4; i++)
            cp_async16(smem_u32(&Bs[(brow + i * 4) * BST + bcol]),
                       Bptr + (size_t)(k0 + i * 4) * N);
        asm volatile("cp.async.commit_group;");
    };

    load_stage(0, 0);
    load_stage(1, 1);

    for (int t = 0; t < NKT; t++) {
        const int s = t % 3;
        if (t < NKT - 1) asm volatile("cp.async.wait_group 1;");
        else             asm volatile("cp.async.wait_group 0;");
        __syncthreads();
        if (t + 2 < NKT) load_stage(t + 2, (t + 2) % 3);

        const float* As = gsm + s * GSTAGE;
        const float* Bs = gsm + s * GSTAGE + A_FLOATS;

        #pragma unroll
        for (int ks = 0; ks < 2; ks++) {
            unsigned a[4][4], b[8][2];
            const int kk = ks * 8 + (lane & 3);
            #pragma unroll
            for (int mf = 0; mf < 4; mf++) {
                unsigned ad = smem_u32(&As[(wm * 64 + mf * 16 + (lane & 15)) * AST
                                           + ks * 8 + ((lane >> 4) << 2)]);
                ldsm_x4(a[mf][0], a[mf][1], a[mf][2], a[mf][3], ad);
            }
            #pragma unroll
            for (int nf = 0; nf < 8; nf++) {
                const int n = wn * 64 + nf * 8 + (lane >> 2);
                b[nf][0] = __float_as_uint(Bs[kk * BST + n]);
                b[nf][1] = __float_as_uint(Bs[(kk + 4) * BST + n]);
            }
            #pragma unroll
            for (int mf = 0; mf < 4; mf++)
                #pragma unroll
                for (int nf = 0; nf < 8; nf++)
                    mma_tf32(acc[mf][nf], a[mf], b[nf]);
        }
        __syncthreads();
    }

    const int r0  = lane >> 2;
    const int c0l = (lane & 3) * 2;
    #pragma unroll
    for (int mf = 0; mf < 4; mf++) {
        const int row = by * GBM + wm * 64 + mf * 16 + r0;
        #pragma unroll
        for (int nf = 0; nf < 8; nf++) {
            const int col = bx * GBN + wn * 64 + nf * 8 + c0l;
            const float2 bb = *(const float2*)&bias[col];
            float v00 = acc[mf][nf][0] + bb.x, v01 = acc[mf][nf][1] + bb.y;
            float v10 = acc[mf][nf][2] + bb.x, v11 = acc[mf][nf][3] + bb.y;
            if (cvt_out) {
                v00 = rnd_tf32(v00); v01 = rnd_tf32(v01);
                v10 = rnd_tf32(v10); v11 = rnd_tf32(v11);
            }
            *(float2*)(C + (size_t)row * N + col)       = make_float2(v00, v01);
            *(float2*)(C + (size_t)(row + 8) * N + col) = make_float2(v10, v11);
        }
    }
}

// ============== Flash attention: 4 warps x 32 q-rows = 128 q/block =========
// Two 16-row fragment sets per warp; K/V frags loaded once, reused x2.
#define AKS 68
#define AVS 72
#define APS 68
#define OFF_VS (2*64*AKS)              // floats
#define OFF_PS (OFF_VS + 2*64*AVS)
#define ATTN_SMEM ((OFF_PS + 4*32*APS) * 4)   // 106496 B

__global__ __launch_bounds__(128, 2)
void attn_mma(const float* __restrict__ qkv, float* __restrict__ y)
{
    extern __shared__ float sm[];
    float* Ks = sm;                 // [2][64][AKS]
    float* Vs = sm + OFF_VS;        // [2][64][AVS]
    float* Ps = sm + OFF_PS;        // [4][32][APS] (+Q staging [128][APS])

    const int b = blockIdx.z, h = blockIdx.y;
    const int qti = gridDim.x - 1 - blockIdx.x;   // heavy blocks first
    const int tid = threadIdx.x, lane = tid & 31, warp = tid >> 5;
    const int g = lane >> 2, cq = lane & 3;
    const int qbase = qti * 128;

    // ---- stage 128 Q rows into Ps, build two register Q frag sets ----
    #pragma unroll
    for (int i = 0; i < 16; i++) {
        int chunk = i * 128 + tid;
        int row = chunk >> 4, col = (chunk & 15) << 2;
        cp_async16(smem_u32(&Ps[row * APS + col]),
                   qkv + (size_t)(b * SEQ + qbase + row) * QKV_N + h * HD + col);
    }
    asm volatile("cp.async.commit_group;");
    asm volatile("cp.async.wait_group 0;");
    __syncthreads();

    unsigned qf[2][8][4];
    #pragma unroll
    for (int hh = 0; hh < 2; hh++) {
        const int qrow = warp * 32 + hh * 16 + (lane & 15);
        const int qcol = (lane >> 4) << 2;
        #pragma unroll
        for (int ks = 0; ks < 8; ks++) {
            ldsm_x4(qf[hh][ks][0], qf[hh][ks][1], qf[hh][ks][2], qf[hh][ks][3],
                    smem_u32(&Ps[qrow * APS + ks * 8 + qcol]));
            #pragma unroll
            for (int i = 0; i < 4; i++)   // fold softmax scale (exact: 2^-3)
                qf[hh][ks][i] = __float_as_uint(__uint_as_float(qf[hh][ks][i]) * 0.125f);
        }
    }

    float o[2][8][4];
    #pragma unroll
    for (int hh = 0; hh < 2; hh++)
        #pragma unroll
        for (int nf = 0; nf < 8; nf++)
            #pragma unroll
            for (int j = 0; j < 4; j++) o[hh][nf][j] = 0.f;
    float mA[2] = {-1e30f, -1e30f}, mB[2] = {-1e30f, -1e30f};
    float lA[2] = {0.f, 0.f},       lB[2] = {0.f, 0.f};

    const int krow_off = (lane & 7) + ((lane >> 4) & 1) * 8;
    const int kcol_off = ((lane >> 3) & 1) * 4;
    const int prow = lane & 15;
    const int pcol = (lane >> 4) << 2;
    float* myP = Ps + warp * 32 * APS;

    auto kv_load = [&](int buf, int kt) {
        #pragma unroll
        for (int i = 0; i < 8; i++) {
            int chunk = i * 128 + tid;
            int row = chunk >> 4, col = (chunk & 15) << 2;
            const float* src = qkv + (size_t)(b * SEQ + kt * 64 + row) * QKV_N
                                   + CH + h * HD + col;
            cp_async16(smem_u32(&Ks[buf * 64 * AKS + row * AKS + col]), src);
            cp_async16(smem_u32(&Vs[buf * 64 * AVS + row * AVS + col]), src + CH);
        }
        asm volatile("cp.async.commit_group;");
    };

    const int NKT = 2 * qti + 2;     // causal tiles for 128-row block
    kv_load(0, 0);

    for (int kt = 0; kt < NKT; kt++) {
        const int buf = kt & 1;
        asm volatile("cp.async.wait_group 0;");
        __syncthreads();
        if (kt + 1 < NKT) kv_load(buf ^ 1, kt + 1);

        // warp-uniform skip: this warp's rows all below this k tile
        if (kt * 64 > qbase + warp * 32 + 31) continue;

        const float* Kb = Ks + buf * 64 * AKS;
        const float* Vb = Vs + buf * 64 * AVS;

        // ---- S = Q @ K^T (both halves share K frags) ----
        float s[2][8][4];
        #pragma unroll
        for (int hh = 0; hh < 2; hh++)
            #pragma unroll
            for (int nf = 0; nf < 8; nf++)
                #pragma unroll
                for (int j = 0; j < 4; j++) s[hh][nf][j] = 0.f;

        #pragma unroll
        for (int ks = 0; ks < 8; ks++) {
            unsigned bf[8][2];
            #pragma unroll
            for (int nfp = 0; nfp < 4; nfp++)
                ldsm_x4(bf[2*nfp][0], bf[2*nfp][1], bf[2*nfp+1][0], bf[2*nfp+1][1],
                        smem_u32(&Kb[(nfp * 16 + krow_off) * AKS + ks * 8 + kcol_off]));
            #pragma unroll
            for (int nf = 0; nf < 8; nf++) {
                mma_tf32(s[0][nf], qf[0][ks], bf[nf]);
                mma_tf32(s[1][nf], qf[1][ks], bf[nf]);
            }
        }

        // ---- causal mask ----
        if (kt * 64 + 63 > qbase + warp * 32) {
            #pragma unroll
            for (int hh = 0; hh < 2; hh++) {
                const int q0 = qbase + warp * 32 + hh * 16 + g;
                const int kb = kt * 64 + 2 * cq;
                #pragma unroll
                for (int nf = 0; nf < 8; nf++) {
                    const int k0 = kb + nf * 8;
                    if (k0     > q0)     s[hh][nf][0] = -1e30f;
                    if (k0 + 1 > q0)     s[hh][nf][1] = -1e30f;
                    if (k0     > q0 + 8) s[hh][nf][2] = -1e30f;
                    if (k0 + 1 > q0 + 8) s[hh][nf][3] = -1e30f;
                }
            }
        }

        // ---- online softmax (per half) ----
        #pragma unroll
        for (int hh = 0; hh < 2; hh++) {
            float mx0 = -1e30f, mx1 = -1e30f;
            #pragma unroll
            for (int nf = 0; nf < 8; nf++) {
                mx0 = fmaxf(mx0, fmaxf(s[hh][nf][0], s[hh][nf][1]));
                mx1 = fmaxf(mx1, fmaxf(s[hh][nf][2], s[hh][nf][3]));
            }
            mx0 = fmaxf(mx0, __shfl_xor_sync(0xffffffffu, mx0, 1));
            mx0 = fmaxf(mx0, __shfl_xor_sync(0xffffffffu, mx0, 2));
            mx1 = fmaxf(mx1, __shfl_xor_sync(0xffffffffu, mx1, 1));
            mx1 = fmaxf(mx1, __shfl_xor_sync(0xffffffffu, mx1, 2));
            const float mn0 = fmaxf(mA[hh], mx0), mn1 = fmaxf(mB[hh], mx1);
            const float coef0 = __expf(mA[hh] - mn0), coef1 = __expf(mB[hh] - mn1);
            mA[hh] = mn0; mB[hh] = mn1;

            float sum0 = 0.f, sum1 = 0.f;
            #pragma unroll
            for (int nf = 0; nf < 8; nf++) {
                s[hh][nf][0] = rnd_tf32(__expf(s[hh][nf][0] - mn0));
                s[hh][nf][1] = rnd_tf32(__expf(s[hh][nf][1] - mn0));
                s[hh][nf][2] = rnd_tf32(__expf(s[hh][nf][2] - mn1));
                s[hh][nf][3] = rnd_tf32(__expf(s[hh][nf][3] - mn1));
                sum0 += s[hh][nf][0] + s[hh][nf][1];
                sum1 += s[hh][nf][2] + s[hh][nf][3];
            }
            sum0 += __shfl_xor_sync(0xffffffffu, sum0, 1);
            sum0 += __shfl_xor_sync(0xffffffffu, sum0, 2);
            sum1 += __shfl_xor_sync(0xffffffffu, sum1, 1);
            sum1 += __shfl_xor_sync(0xffffffffu, sum1, 2);
            lA[hh] = lA[hh] * coef0 + sum0;
            lB[hh] = lB[hh] * coef1 + sum1;

            #pragma unroll
            for (int nf = 0; nf < 8; nf++) {
                o[hh][nf][0] *= coef0; o[hh][nf][1] *= coef0;
                o[hh][nf][2] *= coef1; o[hh][nf][3] *= coef1;
            }

            // P: C-frag -> smem (A-frag staging)
            #pragma unroll
            for (int nf = 0; nf < 8; nf++) {
                *(float2*)&myP[(hh*16 + g) * APS + nf * 8 + 2 * cq] =
                    make_float2(s[hh][nf][0], s[hh][nf][1]);
                *(float2*)&myP[(hh*16 + g + 8) * APS + nf * 8 + 2 * cq] =
                    make_float2(s[hh][nf][2], s[hh][nf][3]);
            }
        }
        __syncwarp();

        // ---- O += P @ V (both halves share V frags) ----
        #pragma unroll
        for (int ks = 0; ks < 8; ks++) {
            unsigned ap0[4], ap1[4];
            ldsm_x4(ap0[0], ap0[1], ap0[2], ap0[3],
                    smem_u32(&myP[prow * APS + ks * 8 + pcol]));
            ldsm_x4(ap1[0], ap1[1], ap1[2], ap1[3],
                    smem_u32(&myP[(16 + prow) * APS + ks * 8 + pcol]));
            #pragma unroll
            for (int nf = 0; nf < 8; nf++) {
                unsigned bv[2];
                bv[0] = __float_as_uint(Vb[(ks * 8 + cq) * AVS + nf * 8 + g]);
                bv[1] = __float_as_uint(Vb[(ks * 8 + 4 + cq) * AVS + nf * 8 + g]);
                mma_tf32(o[0][nf], ap0, bv);
                mma_tf32(o[1][nf], ap1, bv);
            }
        }
        __syncwarp();
    }

    // ---- epilogue (tf32-rounded so proj consumes without cvt) ----
    #pragma unroll
    for (int hh = 0; hh < 2; hh++) {
        const float inv0 = 1.f / lA[hh], inv1 = 1.f / lB[hh];
        const int row0 = qbase + warp * 32 + hh * 16 + g;
        float* y0 = y + (size_t)(b * SEQ + row0) * CH + h * HD;
        float* y1 = y0 + (size_t)8 * CH;
        #pragma unroll
        for (int nf = 0; nf < 8; nf++) {
            const int col = nf * 8 + 2 * cq;
            *(float2*)&y0[col] = make_float2(rnd_tf32(o[hh][nf][0] * inv0),
                                             rnd_tf32(o[hh][nf][1] * inv0));
            *(float2*)&y1[col] = make_float2(rnd_tf32(o[hh][nf][2] * inv1),
                                             rnd_tf32(o[hh][nf][3] * inv1));
        }
    }
}

// ---------------- launch --------------------------------------------------
extern "C" void kernel_launch(void* const* d_in, const int* in_sizes, int n_in,
                              void* d_out, int out_size)
{
    const float* x      = (const float*)d_in[0];
    const float* w_qkv  = (const float*)d_in[1];
    const float* b_qkv  = (const float*)d_in[2];
    const float* w_proj = (const float*)d_in[3];
    const float* b_proj = (const float*)d_in[4];
    float* out = (float*)d_out;

    float *qkv, *y, *xr, *wqkvr, *wprojr;
    cudaGetSymbolAddress((void**)&qkv,    g_qkv);
    cudaGetSymbolAddress((void**)&y,      g_y);
    cudaGetSymbolAddress((void**)&xr,     g_xr);
    cudaGetSymbolAddress((void**)&wqkvr,  g_wqkv);
    cudaGetSymbolAddress((void**)&wprojr, g_wproj);

    cudaFuncSetAttribute(gemm_tf32, cudaFuncAttributeMaxDynamicSharedMemorySize, GEMM_SMEM);
    cudaFuncSetAttribute(attn_mma, cudaFuncAttributeMaxDynamicSharedMemorySize, ATTN_SMEM);

    // 0) pre-round inputs to tf32
    {
        int n;
        n = M_ROWS * CH / 4;
        round_tf32_kernel<<<(n + 255) / 256, 256>>>(x, xr, n);
        n = CH * QKV_N / 4;
        round_tf32_kernel<<<(n + 255) / 256, 256>>>(w_qkv, wqkvr, n);
        n = CH * CH / 4;
        round_tf32_kernel<<<(n + 255) / 256, 256>>>(w_proj, wprojr, n);
    }

    // 1) QKV GEMM (+tf32 rounding of outputs)
    {
        dim3 grid(QKV_N / GBN, M_ROWS / GBM);
        gemm_tf32<<<grid, 128, GEMM_SMEM>>>(xr, wqkvr, b_qkv, qkv, M_ROWS, QKV_N, CH, 1);
    }

    // 2) causal flash attention (128 q-rows/block, K/V frag reuse x2)
    {
        dim3 grid(SEQ / 128, NH, BATCH);
        attn_mma<<<grid, 128, ATTN_SMEM>>>(qkv, y);
    }

    // 3) proj GEMM
    {
        dim3 grid(CH / GBN, M_ROWS / GBM);
        gemm_tf32<<<grid, 128, GEMM_SMEM>>>(y, wprojr, b_proj, out, M_ROWS, CH, CH, 0);
    }
}